// round 7
// baseline (speedup 1.0000x reference)
#include <cuda_runtime.h>
#include <math.h>
#include <stdint.h>

#define NT 512
#define LD 132
#define O_X  0
#define O_X0 8448
#define O_ZS 16896
#define O_ZA 25344
#define O_XF 33792
#define O_R  41984
#define SMF  42240

__device__ float g_W2[3][512][128];          // rna-rounded; rows 384..511 = folded H
__device__ float g_feat[512][4][256 * 32];   // [b][quad][(il*8+f)*32 + jl], rna-rounded

static __device__ __forceinline__ unsigned rna(float v) {
    unsigned u; asm("cvt.rna.tf32.f32 %0,%1;" : "=r"(u) : "f"(v)); return u;
}
static __device__ __forceinline__ float rnaf(float v) { return __uint_as_float(rna(v)); }
static __device__ __forceinline__ unsigned fau(float v) { return __float_as_uint(v); }

static __device__ __forceinline__ void mma8(float* d, const unsigned* a, unsigned b0, unsigned b1) {
    asm volatile("mma.sync.aligned.m16n8k8.row.col.f32.tf32.tf32.f32 "
                 "{%0,%1,%2,%3},{%4,%5,%6,%7},{%8,%9},{%0,%1,%2,%3};"
                 : "+f"(d[0]), "+f"(d[1]), "+f"(d[2]), "+f"(d[3])
                 : "r"(a[0]), "r"(a[1]), "r"(a[2]), "r"(a[3]), "r"(b0), "r"(b1));
}

__global__ void prep(const float* __restrict__ et, const int* __restrict__ at,
                     const float* __restrict__ wn, const float* __restrict__ wu)
{
    int k = blockIdx.x, l = blockIdx.y, e = threadIdx.x;
    float v;
    if (k < 384) {
        v = wu[((size_t)l * 512 + k) * 128 + e];
    } else {
        int k2 = k - 384, n = k2 >> 3, f = k2 & 7;
        const float* y  = et + at[n] * 128;
        const float* wf = wn + (l * 8 + f) * 128;
        const float* w3 = wu + ((size_t)l * 512 + 384) * 128;
        float a = 0.f;
        #pragma unroll 4
        for (int d = 0; d < 128; d++) a = fmaf(wf[d] * y[d], w3[(size_t)d * 128 + e], a);
        v = a;
    }
    g_W2[l][k][e] = rnaf(v);
}

__global__ void __launch_bounds__(NT) gnn(
    const float* __restrict__ r, const float* __restrict__ Rn,
    const float* __restrict__ ws, const float* __restrict__ wa,
    const float* __restrict__ bu, float* __restrict__ out)
{
    extern __shared__ float sm[];
    const int b = blockIdx.x, tid = threadIdx.x, w = tid >> 5, ln = tid & 31;
    const int g = ln >> 2, t = ln & 3;
    const float DEL = 4.0f / 7.0f;
    float S[7];
    #pragma unroll
    for (int k = 0; k < 7; k++) S[k] = expf(-DEL * DEL * (float)(2 * k + 1));

    if (tid < 192) { int i = tid / 3, c = tid % 3; sm[O_R + i * 4 + c] = r[((size_t)b * 64 + i) * 3 + c]; }
    __syncthreads();

    // x0: raw into XF, rounded into X and X0 panels
    for (int p = tid; p < 1024; p += NT) {
        int i = p >> 4, n = p & 15;
        float dx = sm[O_R + i * 4]     - Rn[((size_t)b * 16 + n) * 3];
        float dy = sm[O_R + i * 4 + 1] - Rn[((size_t)b * 16 + n) * 3 + 1];
        float dz = sm[O_R + i * 4 + 2] - Rn[((size_t)b * 16 + n) * 3 + 2];
        float d2 = fmaf(dx, dx, fmaf(dy, dy, dz * dz)) + 1e-12f;
        float ft = __expf(-d2), q = __expf(2.f * DEL * sqrtf(d2));
        #pragma unroll
        for (int f = 0; f < 8; f++) {
            int k = n * 8 + f;
            sm[O_XF + i * 128 + k] = ft;
            float fv = rnaf(ft);
            sm[O_X + i * LD + k] = fv;
            sm[O_X0 + i * LD + k] = fv;
            if (f < 7) ft = ft * q * S[f];
        }
    }
    // ee features (layer-invariant, diag-masked) -> global quadrant panels
    for (int p = tid; p < 4096; p += NT) {
        int i = p >> 6, j = p & 63;
        float dx = sm[O_R + i * 4]     - sm[O_R + j * 4];
        float dy = sm[O_R + i * 4 + 1] - sm[O_R + j * 4 + 1];
        float dz = sm[O_R + i * 4 + 2] - sm[O_R + j * 4 + 2];
        float d2 = fmaf(dx, dx, fmaf(dy, dy, dz * dz)) + 1e-12f;
        float ft = (i == j) ? 0.f : __expf(-d2);
        float q = __expf(2.f * DEL * sqrtf(d2));
        float* gq = &g_feat[b][(i >> 5) * 2 + (j >> 5)][0];
        int il = i & 31, jl = j & 31;
        #pragma unroll
        for (int f = 0; f < 8; f++) {
            gq[(il * 8 + f) * 32 + jl] = rnaf(ft);
            if (f < 7) ft = ft * q * S[f];
        }
    }
    __syncthreads();

    for (int l = 0; l < 3; l++) {
        // ===== GEMM1: z panels via tf32 mma, warp w owns rowtile rt=w =====
        #pragma unroll 1
        for (int q = 0; q < 4; q++) {
            int iblk = q >> 1, jblk = q & 1, same = (iblk == jblk);
            const float* Aq = &g_feat[b][q][0];
            const float* we = (same ? ws : wa) + l * 1024;
            float* zp = sm + (same ? O_ZS : O_ZA);
            int rt = w, m0 = rt * 16 + g;
            unsigned a[4][4];
            #pragma unroll
            for (int ks = 0; ks < 4; ks++) {
                int kk = ks * 8 + t;
                a[ks][0] = fau(Aq[m0 * 32 + kk]);
                a[ks][1] = fau(Aq[(m0 + 8) * 32 + kk]);
                a[ks][2] = fau(Aq[m0 * 32 + kk + 4]);
                a[ks][3] = fau(Aq[(m0 + 8) * 32 + kk + 4]);
            }
            #pragma unroll 1
            for (int ct = 0; ct < 16; ct++) {
                float acc[4] = {0.f, 0.f, 0.f, 0.f};
                #pragma unroll
                for (int ks = 0; ks < 4; ks++) {
                    int j0 = jblk * 32 + ks * 8 + t;
                    unsigned b0 = fau(sm[O_X + j0 * LD + ct * 8 + g]);
                    unsigned b1 = fau(sm[O_X + (j0 + 4) * LD + ct * 8 + g]);
                    mma8(acc, a[ks], b0, b1);
                }
                int d0 = ct * 8 + 2 * t;
                float w0 = we[g * 128 + d0], w1 = we[g * 128 + d0 + 1];
                float v0 = acc[0] * w0, v1 = acc[1] * w1, v2 = acc[2] * w0, v3 = acc[3] * w1;
                #pragma unroll
                for (int s = 4; s < 32; s <<= 1) {
                    v0 += __shfl_xor_sync(0xffffffffu, v0, s);
                    v1 += __shfl_xor_sync(0xffffffffu, v1, s);
                    v2 += __shfl_xor_sync(0xffffffffu, v2, s);
                    v3 += __shfl_xor_sync(0xffffffffu, v3, s);
                }
                if (ln < 4) {
                    int e0 = iblk * 32 + rt * 2, dd = ct * 8 + 2 * ln;
                    zp[e0 * LD + dd]       = rnaf(v0);
                    zp[e0 * LD + dd + 1]   = rnaf(v1);
                    zp[(e0 + 1) * LD + dd]     = rnaf(v2);
                    zp[(e0 + 1) * LD + dd + 1] = rnaf(v3);
                }
            }
        }
        __syncthreads();

        // ===== GEMM2: pre[i,e] = sum_src A_src @ W2_src =====
        const int rt2 = w >> 2, nq = w & 3, i0 = rt2 * 16 + g;
        float acc2[4][4];
        #pragma unroll
        for (int nt = 0; nt < 4; nt++)
            #pragma unroll
            for (int c = 0; c < 4; c++) acc2[nt][c] = 0.f;
        const float* W2 = &g_W2[l][0][0];
        #pragma unroll 1
        for (int src = 0; src < 4; src++) {
            const float* Ap = sm + (src == 0 ? O_X : src == 1 ? O_ZS : src == 2 ? O_ZA : O_X0);
            #pragma unroll 1
            for (int ks = 0; ks < 16; ks++) {
                int kk = ks * 8 + t;
                unsigned a2[4] = {
                    fau(Ap[i0 * LD + kk]),       fau(Ap[(i0 + 8) * LD + kk]),
                    fau(Ap[i0 * LD + kk + 4]),   fau(Ap[(i0 + 8) * LD + kk + 4])};
                int krow = src * 128 + ks * 8 + t;
                #pragma unroll
                for (int nt = 0; nt < 4; nt++) {
                    int e = nq * 32 + nt * 8 + g;
                    unsigned b0 = fau(W2[(size_t)krow * 128 + e]);
                    unsigned b1 = fau(W2[(size_t)(krow + 4) * 128 + e]);
                    mma8(acc2[nt], a2, b0, b1);
                }
            }
        }
        __syncthreads();   // all panel reads complete before overwrite

        // epilogue: x += tanh(pre + b); write rounded X panel (or out on last layer)
        #pragma unroll
        for (int nt = 0; nt < 4; nt++) {
            int e = nq * 32 + nt * 8 + 2 * t;
            float b0v = bu[l * 128 + e], b1v = bu[l * 128 + e + 1];
            float n00 = sm[O_XF + i0 * 128 + e]           + tanhf(acc2[nt][0] + b0v);
            float n01 = sm[O_XF + i0 * 128 + e + 1]       + tanhf(acc2[nt][1] + b1v);
            float n10 = sm[O_XF + (i0 + 8) * 128 + e]     + tanhf(acc2[nt][2] + b0v);
            float n11 = sm[O_XF + (i0 + 8) * 128 + e + 1] + tanhf(acc2[nt][3] + b1v);
            if (l < 2) {
                sm[O_XF + i0 * 128 + e] = n00;           sm[O_XF + i0 * 128 + e + 1] = n01;
                sm[O_XF + (i0 + 8) * 128 + e] = n10;     sm[O_XF + (i0 + 8) * 128 + e + 1] = n11;
                sm[O_X + i0 * LD + e] = rnaf(n00);       sm[O_X + i0 * LD + e + 1] = rnaf(n01);
                sm[O_X + (i0 + 8) * LD + e] = rnaf(n10); sm[O_X + (i0 + 8) * LD + e + 1] = rnaf(n11);
            } else {
                out[((size_t)b * 64 + i0) * 128 + e] = n00;
                out[((size_t)b * 64 + i0) * 128 + e + 1] = n01;
                out[((size_t)b * 64 + i0 + 8) * 128 + e] = n10;
                out[((size_t)b * 64 + i0 + 8) * 128 + e + 1] = n11;
            }
        }
        __syncthreads();
    }
}

extern "C" void kernel_launch(void* const* d_in, const int* in_sizes, int n_in,
                              void* d_out, int out_size)
{
    const float* r  = (const float*)d_in[0];
    const float* Rn = (const float*)d_in[1];
    const float* et = (const float*)d_in[2];
    const float* ws = (const float*)d_in[3];
    const float* wa = (const float*)d_in[4];
    const float* wn = (const float*)d_in[5];
    const float* wu = (const float*)d_in[6];
    const float* bu = (const float*)d_in[7];
    const int*   at = (const int*)d_in[8];
    float* out = (float*)d_out;

    const int smem = SMF * (int)sizeof(float);   // 168,960 B
    cudaFuncSetAttribute(gnn, cudaFuncAttributeMaxDynamicSharedMemorySize, smem);
    prep<<<dim3(512, 3), 128>>>(et, at, wn, wu);
    gnn<<<512, NT, smem>>>(r, Rn, ws, wa, bu, out);
}

// round 9
// speedup vs baseline: 2.1633x; 2.1633x over previous
#include <cuda_runtime.h>
#include <math.h>
#include <stdint.h>

#define NT 512
// ---- smem float offsets ----
// d-paired panels: row = 65 float2 = 130 floats; pairs (d, d+4) within 8-blocks
//   element d at pp=(d>>3)*4+(d&3), cp=(d>>2)&1
// XTP (j-paired): row = 33 float2 = 66 floats, j in 0..63 -> pj in 0..31
#define O_XP  0        // x    [64][65 f2]   8320
#define O_X0P 8320     // x0   [64][65 f2]   8320
#define O_ZSP 16640    // z_s  [64][65 f2]   8320
#define O_ZAP 24960    // z_a  [64][65 f2]   8320
#define O_XTP 33280    // x^T  [128][33 f2]  8448
#define O_XF  41728    // x raw [64][128]    8192
#define O_WE  49920    // we_same[8][128], we_anti[8][128]  2048
#define O_R   51968    // positions [64][4]   256
#define SMF   52224    // 208,896 bytes

__device__ float g_fp[512][32768];     // feat paired: [b][q][(f*32+il)*32 + pj*2+cj]
__device__ float g_W2P[3][65536];      // W2 paired-frag: [l][pk(256)][e(128) f2]

static __device__ __forceinline__ unsigned rna(float v) {
    unsigned u; asm("cvt.rna.tf32.f32 %0,%1;" : "=r"(u) : "f"(v)); return u;
}
static __device__ __forceinline__ float rnaf(float v) { return __uint_as_float(rna(v)); }
static __device__ __forceinline__ unsigned fau(float v) { return __float_as_uint(v); }

static __device__ __forceinline__ void mma8(float* d, const unsigned* a, unsigned b0, unsigned b1) {
    asm volatile("mma.sync.aligned.m16n8k8.row.col.f32.tf32.tf32.f32 "
                 "{%0,%1,%2,%3},{%4,%5,%6,%7},{%8,%9},{%0,%1,%2,%3};"
                 : "+f"(d[0]), "+f"(d[1]), "+f"(d[2]), "+f"(d[3])
                 : "r"(a[0]), "r"(a[1]), "r"(a[2]), "r"(a[3]), "r"(b0), "r"(b1));
}

// ---------------------------------------------------------------------------
__global__ void prep(const float* __restrict__ et, const int* __restrict__ at,
                     const float* __restrict__ wn, const float* __restrict__ wu)
{
    int k = blockIdx.x, l = blockIdx.y, e = threadIdx.x;
    float v;
    if (k < 384) {
        v = wu[((size_t)l * 512 + k) * 128 + e];
    } else {
        int k2 = k - 384, n = k2 >> 3, f = k2 & 7;
        const float* y  = et + at[n] * 128;
        const float* wf = wn + (l * 8 + f) * 128;
        const float* w3 = wu + ((size_t)l * 512 + 384) * 128;
        float a = 0.f;
        #pragma unroll 4
        for (int d = 0; d < 128; d++) a = fmaf(wf[d] * y[d], w3[(size_t)d * 128 + e], a);
        v = a;
    }
    int t2 = k & 3, cp = (k >> 2) & 1, ks = (k & 127) >> 3, src = k >> 7;
    int pk = src * 64 + ks * 4 + t2;
    g_W2P[l][pk * 256 + e * 2 + cp] = rnaf(v);
}

// ---------------------------------------------------------------------------
__global__ void __launch_bounds__(NT) gnn(
    const float* __restrict__ r, const float* __restrict__ Rn,
    const float* __restrict__ ws, const float* __restrict__ wa,
    const float* __restrict__ bu, float* __restrict__ out)
{
    extern __shared__ float sm[];
    const int b = blockIdx.x, tid = threadIdx.x, w = tid >> 5, ln = tid & 31;
    const int g = ln >> 2, t = ln & 3;
    const float DEL = 4.0f / 7.0f;
    float S[7];
    #pragma unroll
    for (int k = 0; k < 7; k++) S[k] = expf(-DEL * DEL * (float)(2 * k + 1));

    if (tid < 192) { int i = tid / 3, c = tid % 3; sm[O_R + i * 4 + c] = r[((size_t)b * 64 + i) * 3 + c]; }
    __syncthreads();

    // ---- x0 into XF (raw) + XP/X0P (d-paired) + XTP (j-paired) ----
    for (int p = tid; p < 1024; p += NT) {
        int i = p >> 4, n = p & 15;
        float dx = sm[O_R + i * 4]     - Rn[((size_t)b * 16 + n) * 3];
        float dy = sm[O_R + i * 4 + 1] - Rn[((size_t)b * 16 + n) * 3 + 1];
        float dz = sm[O_R + i * 4 + 2] - Rn[((size_t)b * 16 + n) * 3 + 2];
        float d2 = fmaf(dx, dx, fmaf(dy, dy, dz * dz)) + 1e-12f;
        float ft = __expf(-d2), q = __expf(2.f * DEL * sqrtf(d2));
        int pi = (i >> 3) * 4 + (i & 3), ci = (i >> 2) & 1;
        #pragma unroll
        for (int f = 0; f < 8; f++) {
            int k = n * 8 + f;
            sm[O_XF + i * 128 + k] = ft;
            float fv = rnaf(ft);
            int pp = n * 4 + (f & 3), cp = (f >> 2) & 1;
            sm[O_XP  + (i * 65 + pp) * 2 + cp] = fv;
            sm[O_X0P + (i * 65 + pp) * 2 + cp] = fv;
            sm[O_XTP + (k * 33 + pi) * 2 + ci] = fv;
            if (f < 7) ft = ft * q * S[f];
        }
    }
    // ---- ee features -> global paired panels (diag masked) ----
    for (int p = tid; p < 4096; p += NT) {
        int i = p >> 6, j = p & 63;
        float dx = sm[O_R + i * 4]     - sm[O_R + j * 4];
        float dy = sm[O_R + i * 4 + 1] - sm[O_R + j * 4 + 1];
        float dz = sm[O_R + i * 4 + 2] - sm[O_R + j * 4 + 2];
        float d2 = fmaf(dx, dx, fmaf(dy, dy, dz * dz)) + 1e-12f;
        float ft = (i == j) ? 0.f : __expf(-d2);
        float q = __expf(2.f * DEL * sqrtf(d2));
        int qd = (i >> 5) * 2 + (j >> 5), il = i & 31, jl = j & 31;
        int pj = (jl >> 3) * 4 + (jl & 3), cj = (jl >> 2) & 1;
        float* gq = &g_fp[b][qd * 8192];
        #pragma unroll
        for (int f = 0; f < 8; f++) {
            gq[(f * 32 + il) * 32 + pj * 2 + cj] = rnaf(ft);
            if (f < 7) ft = ft * q * S[f];
        }
    }
    __syncthreads();

    for (int l = 0; l < 3; l++) {
        // stage we
        for (int p = tid; p < 2048; p += NT)
            sm[O_WE + p] = (p < 1024) ? ws[l * 1024 + p] : wa[l * 1024 + p - 1024];
        __syncthreads();

        // ===== GEMM1: per-f mma, zero shuffles =====
        {
            const int wm = w & 1, wd = w >> 1;   // 2 m-tiles x 8 d-tiles
            #pragma unroll 1
            for (int q = 0; q < 4; q++) {
                const int iblk = q >> 1, jblk = q & 1, same = (iblk == jblk);
                // preload B frags: x^T pairs over j
                float2 Bf[4][2];
                #pragma unroll
                for (int ks = 0; ks < 4; ks++)
                    #pragma unroll
                    for (int nt = 0; nt < 2; nt++)
                        Bf[ks][nt] = *(const float2*)&sm[O_XTP +
                            ((wd * 16 + nt * 8 + g) * 33 + jblk * 16 + ks * 4 + t) * 2];

                float z[2][4] = {{0,0,0,0},{0,0,0,0}};
                const float* gq = &g_fp[b][q * 8192];
                const int weo = O_WE + (same ? 0 : 1024);

                #pragma unroll 2
                for (int f = 0; f < 8; f++) {
                    float2 wv0 = *(const float2*)&sm[weo + f * 128 + wd * 16 + 2 * t];
                    float2 wv1 = *(const float2*)&sm[weo + f * 128 + wd * 16 + 8 + 2 * t];
                    float tf0[4] = {0,0,0,0}, tf1[4] = {0,0,0,0};
                    #pragma unroll
                    for (int ks = 0; ks < 4; ks++) {
                        const float* fr = gq + (f * 32 + wm * 16 + g) * 32 + (ks * 4 + t) * 2;
                        float2 aLo = *(const float2*)fr;
                        float2 aHi = *(const float2*)(fr + 256);
                        unsigned a[4] = {fau(aLo.x), fau(aHi.x), fau(aLo.y), fau(aHi.y)};
                        mma8(tf0, a, fau(Bf[ks][0].x), fau(Bf[ks][0].y));
                        mma8(tf1, a, fau(Bf[ks][1].x), fau(Bf[ks][1].y));
                    }
                    z[0][0] = fmaf(wv0.x, tf0[0], z[0][0]);
                    z[0][1] = fmaf(wv0.y, tf0[1], z[0][1]);
                    z[0][2] = fmaf(wv0.x, tf0[2], z[0][2]);
                    z[0][3] = fmaf(wv0.y, tf0[3], z[0][3]);
                    z[1][0] = fmaf(wv1.x, tf1[0], z[1][0]);
                    z[1][1] = fmaf(wv1.y, tf1[1], z[1][1]);
                    z[1][2] = fmaf(wv1.x, tf1[2], z[1][2]);
                    z[1][3] = fmaf(wv1.y, tf1[3], z[1][3]);
                }
                // store z into d-paired panel (every lane stores 8 values)
                const int zpo = same ? O_ZSP : O_ZAP;
                #pragma unroll
                for (int nt = 0; nt < 2; nt++)
                    #pragma unroll
                    for (int c = 0; c < 4; c++) {
                        int d = wd * 16 + nt * 8 + 2 * t + (c & 1);
                        int row = iblk * 32 + wm * 16 + g + ((c >> 1) ? 8 : 0);
                        int pp = (d >> 3) * 4 + (d & 3), cp = (d >> 2) & 1;
                        sm[zpo + (row * 65 + pp) * 2 + cp] = rnaf(z[nt][c]);
                    }
            }
        }
        __syncthreads();

        // ===== GEMM2: pre = cat @ W2 (K=512), paired frags =====
        const int rt2 = w >> 2, nq = w & 3, ibase = rt2 * 16 + g;
        float acc2[4][4];
        #pragma unroll
        for (int nt = 0; nt < 4; nt++)
            #pragma unroll
            for (int c = 0; c < 4; c++) acc2[nt][c] = 0.f;

        #pragma unroll 1
        for (int src = 0; src < 4; src++) {
            const int apo = (src == 0) ? O_XP : (src == 1) ? O_ZSP : (src == 2) ? O_ZAP : O_X0P;
            const float* Wp = &g_W2P[l][src * 64 * 256];
            #pragma unroll 4
            for (int ks = 0; ks < 16; ks++) {
                float2 aLo = *(const float2*)&sm[apo + (ibase * 65 + ks * 4 + t) * 2];
                float2 aHi = *(const float2*)&sm[apo + ((ibase + 8) * 65 + ks * 4 + t) * 2];
                unsigned a[4] = {fau(aLo.x), fau(aHi.x), fau(aLo.y), fau(aHi.y)};
                const float* wrow = Wp + (ks * 4 + t) * 256;
                #pragma unroll
                for (int nt = 0; nt < 4; nt++) {
                    int e = nq * 32 + nt * 8 + g;
                    float2 bb = *(const float2*)&wrow[e * 2];
                    mma8(acc2[nt], a, fau(bb.x), fau(bb.y));
                }
            }
        }
        __syncthreads();   // panel reads done before overwrite

        // ===== epilogue: x += tanh(pre + b) =====
        const int pi0 = rt2 * 8 + (g & 3), pi1 = rt2 * 8 + 4 + (g & 3), cgi = (g >> 2) & 1;
        #pragma unroll
        for (int nt = 0; nt < 4; nt++) {
            int e = nq * 32 + nt * 8 + 2 * t;
            float b0v = bu[l * 128 + e], b1v = bu[l * 128 + e + 1];
            float n00 = sm[O_XF + ibase * 128 + e]           + tanhf(acc2[nt][0] + b0v);
            float n01 = sm[O_XF + ibase * 128 + e + 1]       + tanhf(acc2[nt][1] + b1v);
            float n10 = sm[O_XF + (ibase + 8) * 128 + e]     + tanhf(acc2[nt][2] + b0v);
            float n11 = sm[O_XF + (ibase + 8) * 128 + e + 1] + tanhf(acc2[nt][3] + b1v);
            if (l < 2) {
                sm[O_XF + ibase * 128 + e] = n00;       sm[O_XF + ibase * 128 + e + 1] = n01;
                sm[O_XF + (ibase + 8) * 128 + e] = n10; sm[O_XF + (ibase + 8) * 128 + e + 1] = n11;
                int pp0 = (nq * 4 + nt) * 4 + ((2 * t) & 3),     c0 = ((2 * t) >> 2) & 1;
                int pp1 = (nq * 4 + nt) * 4 + ((2 * t + 1) & 3), c1 = ((2 * t + 1) >> 2) & 1;
                sm[O_XP + (ibase * 65 + pp0) * 2 + c0] = rnaf(n00);
                sm[O_XP + (ibase * 65 + pp1) * 2 + c1] = rnaf(n01);
                sm[O_XP + ((ibase + 8) * 65 + pp0) * 2 + c0] = rnaf(n10);
                sm[O_XP + ((ibase + 8) * 65 + pp1) * 2 + c1] = rnaf(n11);
                sm[O_XTP + (e * 33 + pi0) * 2 + cgi]       = rnaf(n00);
                sm[O_XTP + ((e + 1) * 33 + pi0) * 2 + cgi] = rnaf(n01);
                sm[O_XTP + (e * 33 + pi1) * 2 + cgi]       = rnaf(n10);
                sm[O_XTP + ((e + 1) * 33 + pi1) * 2 + cgi] = rnaf(n11);
            } else {
                out[((size_t)b * 64 + ibase) * 128 + e]           = n00;
                out[((size_t)b * 64 + ibase) * 128 + e + 1]       = n01;
                out[((size_t)b * 64 + ibase + 8) * 128 + e]       = n10;
                out[((size_t)b * 64 + ibase + 8) * 128 + e + 1]   = n11;
            }
        }
        __syncthreads();
    }
}

extern "C" void kernel_launch(void* const* d_in, const int* in_sizes, int n_in,
                              void* d_out, int out_size)
{
    const float* r  = (const float*)d_in[0];
    const float* Rn = (const float*)d_in[1];
    const float* et = (const float*)d_in[2];
    const float* ws = (const float*)d_in[3];
    const float* wa = (const float*)d_in[4];
    const float* wn = (const float*)d_in[5];
    const float* wu = (const float*)d_in[6];
    const float* bu = (const float*)d_in[7];
    const int*   at = (const int*)d_in[8];
    float* out = (float*)d_out;

    const int smem = SMF * (int)sizeof(float);   // 208,896 B
    cudaFuncSetAttribute(gnn, cudaFuncAttributeMaxDynamicSharedMemorySize, smem);
    prep<<<dim3(512, 3), 128>>>(et, at, wn, wu);
    gnn<<<512, NT, smem>>>(r, Rn, ws, wa, bu, out);
}

// round 10
// speedup vs baseline: 2.3476x; 1.0852x over previous
#include <cuda_runtime.h>
#include <math.h>
#include <stdint.h>

#define NT 512
// ---- smem float offsets ----
// fragment-quad panels: float4 QIDX(i16,g,ks,t) = (i16*8+g)*68 + ks*4 + t
//   comps: 0:(row+0,k) 1:(row+8,k) 2:(row+0,k+4) 3:(row+8,k+4)
#define O_XQ  0        // x    quads: 32*68 f4 = 8704 floats
#define O_X0Q 8704
#define O_ZSQ 17408    // (also reused once as raw-x0 staging [i*128+k])
#define O_ZAQ 26112
#define O_XTP 34816    // x^T j-paired [128][33 f2] = 8448
#define O_WE  43264    // we_same[8][128] + we_anti[8][128]
#define O_R   45312
#define SMF   45568    // 182,272 B

__device__ float g_fq[512][32768];    // feat fragment-quads per batch/quadrant
__device__ float g_W2Q[3][65536];     // W2 fragment-quads (B side, 2 n-tiles per quad)

static __device__ __forceinline__ unsigned rna(float v) {
    unsigned u; asm("cvt.rna.tf32.f32 %0,%1;" : "=r"(u) : "f"(v)); return u;
}
static __device__ __forceinline__ float rnaf(float v) { return __uint_as_float(rna(v)); }
static __device__ __forceinline__ unsigned fau(float v) { return __float_as_uint(v); }

static __device__ __forceinline__ void mma8(float* d, const unsigned* a, unsigned b0, unsigned b1) {
    asm volatile("mma.sync.aligned.m16n8k8.row.col.f32.tf32.tf32.f32 "
                 "{%0,%1,%2,%3},{%4,%5,%6,%7},{%8,%9},{%0,%1,%2,%3};"
                 : "+f"(d[0]), "+f"(d[1]), "+f"(d[2]), "+f"(d[3])
                 : "r"(a[0]), "r"(a[1]), "r"(a[2]), "r"(a[3]), "r"(b0), "r"(b1));
}

// ---------------------------------------------------------------------------
__global__ void prep(const float* __restrict__ et, const int* __restrict__ at,
                     const float* __restrict__ wn, const float* __restrict__ wu)
{
    int k = blockIdx.x, l = blockIdx.y, e = threadIdx.x;
    float v;
    if (k < 384) {
        v = wu[((size_t)l * 512 + k) * 128 + e];
    } else {
        int k2 = k - 384, n = k2 >> 3, f = k2 & 7;
        const float* y  = et + at[n] * 128;
        const float* wf = wn + (l * 8 + f) * 128;
        const float* w3 = wu + ((size_t)l * 512 + 384) * 128;
        float a = 0.f;
        #pragma unroll 4
        for (int d = 0; d < 128; d++) a = fmaf(wf[d] * y[d], w3[(size_t)d * 128 + e], a);
        v = a;
    }
    int src = k >> 7, kr = k & 127, ks = kr >> 3, kt = kr & 7, t = kt & 3, cf = kt >> 2;
    int nq = e >> 5, ntp = (e >> 4) & 1, eh = (e >> 3) & 1, g = e & 7;
    int quad = ((((src * 16 + ks) * 4 + t) * 2 + ntp) * 4 + nq) * 8 + g;
    g_W2Q[l][quad * 4 + cf + 2 * eh] = rnaf(v);
}

// ---------------------------------------------------------------------------
__global__ void __launch_bounds__(NT) gnn(
    const float* __restrict__ r, const float* __restrict__ Rn,
    const float* __restrict__ ws, const float* __restrict__ wa,
    const float* __restrict__ bu, float* __restrict__ out)
{
    extern __shared__ __align__(16) float sm[];
    const int b = blockIdx.x, tid = threadIdx.x, w = tid >> 5, ln = tid & 31;
    const int g = ln >> 2, t = ln & 3;
    const int rt2 = w >> 2, nq = w & 3, ibase = rt2 * 16 + g;
    const float DEL = 4.0f / 7.0f;
    float S[7];
    #pragma unroll
    for (int k = 0; k < 7; k++) S[k] = expf(-DEL * DEL * (float)(2 * k + 1));

    if (tid < 192) { int i = tid / 3, c = tid % 3; sm[O_R + i * 4 + c] = r[((size_t)b * 64 + i) * 3 + c]; }
    __syncthreads();

    // ---- x0: raw staging (ZSQ region) + XQ/X0Q quads + XTP ----
    for (int p = tid; p < 1024; p += NT) {
        int i = p >> 4, n = p & 15;
        float dx = sm[O_R + i * 4]     - Rn[((size_t)b * 16 + n) * 3];
        float dy = sm[O_R + i * 4 + 1] - Rn[((size_t)b * 16 + n) * 3 + 1];
        float dz = sm[O_R + i * 4 + 2] - Rn[((size_t)b * 16 + n) * 3 + 2];
        float d2 = fmaf(dx, dx, fmaf(dy, dy, dz * dz)) + 1e-12f;
        float ft = __expf(-d2), q = __expf(2.f * DEL * sqrtf(d2));
        int i16 = i >> 4, g2 = i & 7, h = (i >> 3) & 1;
        int pi = (i >> 3) * 4 + (i & 3), ci = (i >> 2) & 1;
        #pragma unroll
        for (int f = 0; f < 8; f++) {
            int k = n * 8 + f;
            sm[O_ZSQ + i * 128 + k] = ft;               // raw staging
            float fv = rnaf(ft);
            int fi = ((i16 * 8 + g2) * 68 + n * 4 + (f & 3)) * 4 + h + 2 * (f >> 2);
            sm[O_XQ + fi]  = fv;
            sm[O_X0Q + fi] = fv;
            sm[O_XTP + (k * 33 + pi) * 2 + ci] = fv;
            if (f < 7) ft = ft * q * S[f];
        }
    }
    // ---- ee features -> global fragment quads ----
    for (int p = tid; p < 4096; p += NT) {
        int i = p >> 6, j = p & 63;
        float dx = sm[O_R + i * 4]     - sm[O_R + j * 4];
        float dy = sm[O_R + i * 4 + 1] - sm[O_R + j * 4 + 1];
        float dz = sm[O_R + i * 4 + 2] - sm[O_R + j * 4 + 2];
        float d2 = fmaf(dx, dx, fmaf(dy, dy, dz * dz)) + 1e-12f;
        float ft = (i == j) ? 0.f : __expf(-d2);
        float q = __expf(2.f * DEL * sqrtf(d2));
        int qd = (i >> 5) * 2 + (j >> 5), il = i & 31, jl = j & 31;
        int wm2 = il >> 4, g2 = il & 7, h = (il >> 3) & 1;
        int ks = jl >> 3, t2 = (jl & 7) & 3, c = (jl & 7) >> 2;
        float* gb = g_fq[b];
        #pragma unroll
        for (int f = 0; f < 8; f++) {
            int fi = (((((qd * 8 + f) * 2 + wm2) * 4 + ks) * 8 + g2) * 4 + t2) * 4 + h + 2 * c;
            gb[fi] = rnaf(ft);
            if (f < 7) ft = ft * q * S[f];
        }
    }
    __syncthreads();

    // ---- raw x residual into registers (thread mapping is layer-invariant) ----
    float xf[16];
    {
        const float* st = sm + O_ZSQ;
        #pragma unroll
        for (int nt = 0; nt < 4; nt++) {
            int e = nq * 32 + nt * 8 + 2 * t;
            xf[nt * 4 + 0] = st[ibase * 128 + e];
            xf[nt * 4 + 1] = st[ibase * 128 + e + 1];
            xf[nt * 4 + 2] = st[(ibase + 8) * 128 + e];
            xf[nt * 4 + 3] = st[(ibase + 8) * 128 + e + 1];
        }
    }

    const float4* sm4 = (const float4*)sm;

    for (int l = 0; l < 3; l++) {
        for (int p = tid; p < 2048; p += NT)
            sm[O_WE + p] = (p < 1024) ? ws[l * 1024 + p] : wa[l * 1024 + p - 1024];
        __syncthreads();

        // ===== GEMM1: per-f mma, quad A frags (1 LDG.128 each) =====
        {
            const int wm = w & 1, wd = w >> 1;
            const float4* gfq4 = (const float4*)g_fq[b];
            #pragma unroll 1
            for (int q = 0; q < 4; q++) {
                const int iblk = q >> 1, jblk = q & 1, same = (iblk == jblk);
                float2 Bf[4][2];
                #pragma unroll
                for (int ks = 0; ks < 4; ks++)
                    #pragma unroll
                    for (int nt = 0; nt < 2; nt++)
                        Bf[ks][nt] = *(const float2*)&sm[O_XTP +
                            ((wd * 16 + nt * 8 + g) * 33 + jblk * 16 + ks * 4 + t) * 2];

                float z[2][4] = {{0,0,0,0},{0,0,0,0}};
                const int weo = O_WE + (same ? 0 : 1024);

                #pragma unroll 2
                for (int f = 0; f < 8; f++) {
                    float2 wv0 = *(const float2*)&sm[weo + f * 128 + wd * 16 + 2 * t];
                    float2 wv1 = *(const float2*)&sm[weo + f * 128 + wd * 16 + 8 + 2 * t];
                    float tf0[4] = {0,0,0,0}, tf1[4] = {0,0,0,0};
                    #pragma unroll
                    for (int ks = 0; ks < 4; ks++) {
                        float4 av = gfq4[((((q * 8 + f) * 2 + wm) * 4 + ks) * 8 + g) * 4 + t];
                        unsigned a[4] = {fau(av.x), fau(av.y), fau(av.z), fau(av.w)};
                        mma8(tf0, a, fau(Bf[ks][0].x), fau(Bf[ks][0].y));
                        mma8(tf1, a, fau(Bf[ks][1].x), fau(Bf[ks][1].y));
                    }
                    z[0][0] = fmaf(wv0.x, tf0[0], z[0][0]);
                    z[0][1] = fmaf(wv0.y, tf0[1], z[0][1]);
                    z[0][2] = fmaf(wv0.x, tf0[2], z[0][2]);
                    z[0][3] = fmaf(wv0.y, tf0[3], z[0][3]);
                    z[1][0] = fmaf(wv1.x, tf1[0], z[1][0]);
                    z[1][1] = fmaf(wv1.y, tf1[1], z[1][1]);
                    z[1][2] = fmaf(wv1.x, tf1[2], z[1][2]);
                    z[1][3] = fmaf(wv1.y, tf1[3], z[1][3]);
                }
                const int zo = (same ? O_ZSQ : O_ZAQ);
                #pragma unroll
                for (int nt = 0; nt < 2; nt++)
                    #pragma unroll
                    for (int cc = 0; cc < 4; cc++) {
                        int kt = 2 * t + (cc & 1), h = cc >> 1;
                        sm[zo + (((iblk * 2 + wm) * 8 + g) * 68 + (wd * 2 + nt) * 4 + (kt & 3)) * 4
                              + h + 2 * (kt >> 2)] = rnaf(z[nt][cc]);
                    }
            }
        }
        __syncthreads();

        // ===== GEMM2: quad A (LDS.128) + quad B (LDG.128, 2 n-tiles each) =====
        float acc2[4][4];
        #pragma unroll
        for (int nt = 0; nt < 4; nt++)
            #pragma unroll
            for (int c = 0; c < 4; c++) acc2[nt][c] = 0.f;

        #pragma unroll 1
        for (int src = 0; src < 4; src++) {
            const int ap4 = ((src == 0) ? O_XQ : (src == 1) ? O_ZSQ : (src == 2) ? O_ZAQ : O_X0Q) >> 2;
            const float4* w2q4 = (const float4*)g_W2Q[l] + src * 4096;
            #pragma unroll 4
            for (int ks = 0; ks < 16; ks++) {
                float4 aq = sm4[ap4 + (rt2 * 8 + g) * 68 + ks * 4 + t];
                unsigned a[4] = {fau(aq.x), fau(aq.y), fau(aq.z), fau(aq.w)};
                #pragma unroll
                for (int ntp = 0; ntp < 2; ntp++) {
                    float4 bv = w2q4[(((ks * 4 + t) * 2 + ntp) * 4 + nq) * 8 + g];
                    mma8(acc2[2 * ntp], a, fau(bv.x), fau(bv.y));
                    mma8(acc2[2 * ntp + 1], a, fau(bv.z), fau(bv.w));
                }
            }
        }
        __syncthreads();

        // ===== epilogue: x += tanh(pre + b), registers hold raw x =====
        const int pi0 = rt2 * 8 + (g & 3), pi1 = rt2 * 8 + 4 + (g & 3), cgi = (g >> 2) & 1;
        #pragma unroll
        for (int nt = 0; nt < 4; nt++) {
            int e = nq * 32 + nt * 8 + 2 * t;
            float b0v = bu[l * 128 + e], b1v = bu[l * 128 + e + 1];
            float n00 = xf[nt * 4 + 0] + tanhf(acc2[nt][0] + b0v);
            float n01 = xf[nt * 4 + 1] + tanhf(acc2[nt][1] + b1v);
            float n10 = xf[nt * 4 + 2] + tanhf(acc2[nt][2] + b0v);
            float n11 = xf[nt * 4 + 3] + tanhf(acc2[nt][3] + b1v);
            xf[nt * 4 + 0] = n00; xf[nt * 4 + 1] = n01;
            xf[nt * 4 + 2] = n10; xf[nt * 4 + 3] = n11;
            if (l < 2) {
                int base = O_XQ + ((rt2 * 8 + g) * 68 + (nq * 4 + nt) * 4) * 4;
                int k0 = 2 * t, k1 = 2 * t + 1;
                sm[base + (k0 & 3) * 4 + 0 + 2 * (k0 >> 2)] = rnaf(n00);
                sm[base + (k1 & 3) * 4 + 0 + 2 * (k1 >> 2)] = rnaf(n01);
                sm[base + (k0 & 3) * 4 + 1 + 2 * (k0 >> 2)] = rnaf(n10);
                sm[base + (k1 & 3) * 4 + 1 + 2 * (k1 >> 2)] = rnaf(n11);
                sm[O_XTP + (e * 33 + pi0) * 2 + cgi]       = rnaf(n00);
                sm[O_XTP + ((e + 1) * 33 + pi0) * 2 + cgi] = rnaf(n01);
                sm[O_XTP + (e * 33 + pi1) * 2 + cgi]       = rnaf(n10);
                sm[O_XTP + ((e + 1) * 33 + pi1) * 2 + cgi] = rnaf(n11);
            } else {
                out[((size_t)b * 64 + ibase) * 128 + e]         = n00;
                out[((size_t)b * 64 + ibase) * 128 + e + 1]     = n01;
                out[((size_t)b * 64 + ibase + 8) * 128 + e]     = n10;
                out[((size_t)b * 64 + ibase + 8) * 128 + e + 1] = n11;
            }
        }
        __syncthreads();
    }
}

extern "C" void kernel_launch(void* const* d_in, const int* in_sizes, int n_in,
                              void* d_out, int out_size)
{
    const float* r  = (const float*)d_in[0];
    const float* Rn = (const float*)d_in[1];
    const float* et = (const float*)d_in[2];
    const float* ws = (const float*)d_in[3];
    const float* wa = (const float*)d_in[4];
    const float* wn = (const float*)d_in[5];
    const float* wu = (const float*)d_in[6];
    const float* bu = (const float*)d_in[7];
    const int*   at = (const int*)d_in[8];
    float* out = (float*)d_out;

    const int smem = SMF * (int)sizeof(float);   // 182,272 B
    cudaFuncSetAttribute(gnn, cudaFuncAttributeMaxDynamicSharedMemorySize, smem);
    prep<<<dim3(512, 3), 128>>>(et, at, wn, wu);
    gnn<<<512, NT, smem>>>(r, Rn, ws, wa, bu, out);
}

// round 11
// speedup vs baseline: 2.7468x; 1.1700x over previous
#include <cuda_runtime.h>
#include <math.h>
#include <stdint.h>

#define NT 1024
// ---- smem float offsets ----
// fragment-quad panels: float4 QIDX = (i16*8+g)*68 + ks*4 + t
//   comps: 0:(row+0,k) 1:(row+8,k) 2:(row+0,k+4) 3:(row+8,k+4)
#define O_XQ  0        // x quads: 32*68 f4 = 8704 floats
#define O_X0Q 8704
#define O_ZSQ 17408    // (also reused once as raw-x0 staging [i*128+k])
#define O_ZAQ 26112
#define O_XTP 34816    // x^T j-paired [128][33 f2] = 8448
#define O_WE  43264    // we_same[8][128] + we_anti[8][128]
#define O_R   45312
#define SMF   45568    // 182,272 B

__device__ float g_fq[512][32768];    // feat fragment-quads per batch/quadrant
__device__ float g_W2Q[3][65536];     // W2 fragment-quads (B side, 2 n-tiles per quad)

static __device__ __forceinline__ unsigned rna(float v) {
    unsigned u; asm("cvt.rna.tf32.f32 %0,%1;" : "=r"(u) : "f"(v)); return u;
}
static __device__ __forceinline__ float rnaf(float v) { return __uint_as_float(rna(v)); }
static __device__ __forceinline__ unsigned fau(float v) { return __float_as_uint(v); }

static __device__ __forceinline__ void mma8(float* d, const unsigned* a, unsigned b0, unsigned b1) {
    asm volatile("mma.sync.aligned.m16n8k8.row.col.f32.tf32.tf32.f32 "
                 "{%0,%1,%2,%3},{%4,%5,%6,%7},{%8,%9},{%0,%1,%2,%3};"
                 : "+f"(d[0]), "+f"(d[1]), "+f"(d[2]), "+f"(d[3])
                 : "r"(a[0]), "r"(a[1]), "r"(a[2]), "r"(a[3]), "r"(b0), "r"(b1));
}

// ---------------------------------------------------------------------------
__global__ void prep(const float* __restrict__ et, const int* __restrict__ at,
                     const float* __restrict__ wn, const float* __restrict__ wu)
{
    int k = blockIdx.x, l = blockIdx.y, e = threadIdx.x;
    float v;
    if (k < 384) {
        v = wu[((size_t)l * 512 + k) * 128 + e];
    } else {
        int k2 = k - 384, n = k2 >> 3, f = k2 & 7;
        const float* y  = et + at[n] * 128;
        const float* wf = wn + (l * 8 + f) * 128;
        const float* w3 = wu + ((size_t)l * 512 + 384) * 128;
        float a = 0.f;
        #pragma unroll 4
        for (int d = 0; d < 128; d++) a = fmaf(wf[d] * y[d], w3[(size_t)d * 128 + e], a);
        v = a;
    }
    int src = k >> 7, kr = k & 127, ks = kr >> 3, kt = kr & 7, t = kt & 3, cf = kt >> 2;
    int nq = e >> 5, ntp = (e >> 4) & 1, eh = (e >> 3) & 1, g = e & 7;
    int quad = ((((src * 16 + ks) * 4 + t) * 2 + ntp) * 4 + nq) * 8 + g;
    g_W2Q[l][quad * 4 + cf + 2 * eh] = rnaf(v);
}

// ---------------------------------------------------------------------------
__global__ void __launch_bounds__(NT) gnn(
    const float* __restrict__ r, const float* __restrict__ Rn,
    const float* __restrict__ ws, const float* __restrict__ wa,
    const float* __restrict__ bu, float* __restrict__ out)
{
    extern __shared__ __align__(16) float sm[];
    const int b = blockIdx.x, tid = threadIdx.x, w = tid >> 5, ln = tid & 31;
    const int g = ln >> 2, t = ln & 3;
    // GEMM2 / epilogue mapping: 2 warps per (rt2,nq) tile, split by n-pair
    const int half = w & 1;
    const int rt2 = w >> 3, nq = (w >> 1) & 3, ibase = rt2 * 16 + g;
    // GEMM1 mapping: warp handles quadrants {qp, qp+2} of tile (wm, wd)
    const int qp = w & 1, wm = (w >> 1) & 1, wd = w >> 2;
    const float DEL = 4.0f / 7.0f;
    float S[7];
    #pragma unroll
    for (int k = 0; k < 7; k++) S[k] = expf(-DEL * DEL * (float)(2 * k + 1));

    if (tid < 192) { int i = tid / 3, c = tid % 3; sm[O_R + i * 4 + c] = r[((size_t)b * 64 + i) * 3 + c]; }
    __syncthreads();

    // ---- x0: raw staging (ZSQ region) + XQ/X0Q quads + XTP ----
    for (int p = tid; p < 1024; p += NT) {
        int i = p >> 4, n = p & 15;
        float dx = sm[O_R + i * 4]     - Rn[((size_t)b * 16 + n) * 3];
        float dy = sm[O_R + i * 4 + 1] - Rn[((size_t)b * 16 + n) * 3 + 1];
        float dz = sm[O_R + i * 4 + 2] - Rn[((size_t)b * 16 + n) * 3 + 2];
        float d2 = fmaf(dx, dx, fmaf(dy, dy, dz * dz)) + 1e-12f;
        float ft = __expf(-d2), q = __expf(2.f * DEL * sqrtf(d2));
        int i16 = i >> 4, g2 = i & 7, h = (i >> 3) & 1;
        int pi = (i >> 3) * 4 + (i & 3), ci = (i >> 2) & 1;
        #pragma unroll
        for (int f = 0; f < 8; f++) {
            int k = n * 8 + f;
            sm[O_ZSQ + i * 128 + k] = ft;               // raw staging
            float fv = rnaf(ft);
            int fi = ((i16 * 8 + g2) * 68 + n * 4 + (f & 3)) * 4 + h + 2 * (f >> 2);
            sm[O_XQ + fi]  = fv;
            sm[O_X0Q + fi] = fv;
            sm[O_XTP + (k * 33 + pi) * 2 + ci] = fv;
            if (f < 7) ft = ft * q * S[f];
        }
    }
    // ---- ee features -> global fragment quads ----
    for (int p = tid; p < 4096; p += NT) {
        int i = p >> 6, j = p & 63;
        float dx = sm[O_R + i * 4]     - sm[O_R + j * 4];
        float dy = sm[O_R + i * 4 + 1] - sm[O_R + j * 4 + 1];
        float dz = sm[O_R + i * 4 + 2] - sm[O_R + j * 4 + 2];
        float d2 = fmaf(dx, dx, fmaf(dy, dy, dz * dz)) + 1e-12f;
        float ft = (i == j) ? 0.f : __expf(-d2);
        float q = __expf(2.f * DEL * sqrtf(d2));
        int qd = (i >> 5) * 2 + (j >> 5), il = i & 31, jl = j & 31;
        int wm2 = il >> 4, g2 = il & 7, h = (il >> 3) & 1;
        int ks = jl >> 3, t2 = (jl & 7) & 3, c = (jl & 7) >> 2;
        float* gb = g_fq[b];
        #pragma unroll
        for (int f = 0; f < 8; f++) {
            int fi = (((((qd * 8 + f) * 2 + wm2) * 4 + ks) * 8 + g2) * 4 + t2) * 4 + h + 2 * c;
            gb[fi] = rnaf(ft);
            if (f < 7) ft = ft * q * S[f];
        }
    }
    __syncthreads();

    // ---- raw x residual into registers: this thread's 8 outputs ----
    float xf[8];
    {
        const float* st = sm + O_ZSQ;
        #pragma unroll
        for (int ntl = 0; ntl < 2; ntl++) {
            int e = nq * 32 + (2 * half + ntl) * 8 + 2 * t;
            xf[ntl * 4 + 0] = st[ibase * 128 + e];
            xf[ntl * 4 + 1] = st[ibase * 128 + e + 1];
            xf[ntl * 4 + 2] = st[(ibase + 8) * 128 + e];
            xf[ntl * 4 + 3] = st[(ibase + 8) * 128 + e + 1];
        }
    }

    const float4* sm4 = (const float4*)sm;

    for (int l = 0; l < 3; l++) {
        for (int p = tid; p < 2048; p += NT)
            sm[O_WE + p] = (p < 1024) ? ws[l * 1024 + p] : wa[l * 1024 + p - 1024];
        __syncthreads();

        // ===== GEMM1: 2 quadrants per warp (same jblk => shared B frags) =====
        {
            const int jblk = qp;
            float2 Bf[4][2];
            #pragma unroll
            for (int ks = 0; ks < 4; ks++)
                #pragma unroll
                for (int nt = 0; nt < 2; nt++)
                    Bf[ks][nt] = *(const float2*)&sm[O_XTP +
                        ((wd * 16 + nt * 8 + g) * 33 + jblk * 16 + ks * 4 + t) * 2];

            const float4* gfq4 = (const float4*)g_fq[b];
            #pragma unroll 1
            for (int qi = 0; qi < 2; qi++) {
                const int iblk = qi, q = iblk * 2 + jblk, same = (iblk == jblk);
                float z[2][4] = {{0,0,0,0},{0,0,0,0}};
                const int weo = O_WE + (same ? 0 : 1024);

                #pragma unroll 2
                for (int f = 0; f < 8; f++) {
                    float2 wv0 = *(const float2*)&sm[weo + f * 128 + wd * 16 + 2 * t];
                    float2 wv1 = *(const float2*)&sm[weo + f * 128 + wd * 16 + 8 + 2 * t];
                    float tf0[4] = {0,0,0,0}, tf1[4] = {0,0,0,0};
                    #pragma unroll
                    for (int ks = 0; ks < 4; ks++) {
                        float4 av = gfq4[((((q * 8 + f) * 2 + wm) * 4 + ks) * 8 + g) * 4 + t];
                        unsigned a[4] = {fau(av.x), fau(av.y), fau(av.z), fau(av.w)};
                        mma8(tf0, a, fau(Bf[ks][0].x), fau(Bf[ks][0].y));
                        mma8(tf1, a, fau(Bf[ks][1].x), fau(Bf[ks][1].y));
                    }
                    z[0][0] = fmaf(wv0.x, tf0[0], z[0][0]);
                    z[0][1] = fmaf(wv0.y, tf0[1], z[0][1]);
                    z[0][2] = fmaf(wv0.x, tf0[2], z[0][2]);
                    z[0][3] = fmaf(wv0.y, tf0[3], z[0][3]);
                    z[1][0] = fmaf(wv1.x, tf1[0], z[1][0]);
                    z[1][1] = fmaf(wv1.y, tf1[1], z[1][1]);
                    z[1][2] = fmaf(wv1.x, tf1[2], z[1][2]);
                    z[1][3] = fmaf(wv1.y, tf1[3], z[1][3]);
                }
                const int zo = (same ? O_ZSQ : O_ZAQ);
                #pragma unroll
                for (int nt = 0; nt < 2; nt++)
                    #pragma unroll
                    for (int cc = 0; cc < 4; cc++) {
                        int kt = 2 * t + (cc & 1), h = cc >> 1;
                        sm[zo + (((iblk * 2 + wm) * 8 + g) * 68 + (wd * 2 + nt) * 4 + (kt & 3)) * 4
                              + h + 2 * (kt >> 2)] = rnaf(z[nt][cc]);
                    }
            }
        }
        __syncthreads();

        // ===== GEMM2: full K=512, only this warp's n-pair (ntp = half) =====
        float acc2[2][4];
        #pragma unroll
        for (int nt = 0; nt < 2; nt++)
            #pragma unroll
            for (int c = 0; c < 4; c++) acc2[nt][c] = 0.f;

        #pragma unroll 1
        for (int src = 0; src < 4; src++) {
            const int ap4 = ((src == 0) ? O_XQ : (src == 1) ? O_ZSQ : (src == 2) ? O_ZAQ : O_X0Q) >> 2;
            const float4* w2q4 = (const float4*)g_W2Q[l] + src * 4096;
            #pragma unroll 4
            for (int ks = 0; ks < 16; ks++) {
                float4 aq = sm4[ap4 + (rt2 * 8 + g) * 68 + ks * 4 + t];
                unsigned a[4] = {fau(aq.x), fau(aq.y), fau(aq.z), fau(aq.w)};
                float4 bv = w2q4[(((ks * 4 + t) * 2 + half) * 4 + nq) * 8 + g];
                mma8(acc2[0], a, fau(bv.x), fau(bv.y));
                mma8(acc2[1], a, fau(bv.z), fau(bv.w));
            }
        }
        __syncthreads();

        // ===== epilogue: x += tanh(pre + b) for this thread's 8 outputs =====
        const int pi0 = rt2 * 8 + (g & 3), pi1 = rt2 * 8 + 4 + (g & 3), cgi = (g >> 2) & 1;
        #pragma unroll
        for (int ntl = 0; ntl < 2; ntl++) {
            int nt = 2 * half + ntl;
            int e = nq * 32 + nt * 8 + 2 * t;
            float b0v = bu[l * 128 + e], b1v = bu[l * 128 + e + 1];
            float n00 = xf[ntl * 4 + 0] + tanhf(acc2[ntl][0] + b0v);
            float n01 = xf[ntl * 4 + 1] + tanhf(acc2[ntl][1] + b1v);
            float n10 = xf[ntl * 4 + 2] + tanhf(acc2[ntl][2] + b0v);
            float n11 = xf[ntl * 4 + 3] + tanhf(acc2[ntl][3] + b1v);
            xf[ntl * 4 + 0] = n00; xf[ntl * 4 + 1] = n01;
            xf[ntl * 4 + 2] = n10; xf[ntl * 4 + 3] = n11;
            if (l < 2) {
                int base = O_XQ + ((rt2 * 8 + g) * 68 + (nq * 4 + nt) * 4) * 4;
                int k0 = 2 * t, k1 = 2 * t + 1;
                sm[base + (k0 & 3) * 4 + 0 + 2 * (k0 >> 2)] = rnaf(n00);
                sm[base + (k1 & 3) * 4 + 0 + 2 * (k1 >> 2)] = rnaf(n01);
                sm[base + (k0 & 3) * 4 + 1 + 2 * (k0 >> 2)] = rnaf(n10);
                sm[base + (k1 & 3) * 4 + 1 + 2 * (k1 >> 2)] = rnaf(n11);
                sm[O_XTP + (e * 33 + pi0) * 2 + cgi]       = rnaf(n00);
                sm[O_XTP + ((e + 1) * 33 + pi0) * 2 + cgi] = rnaf(n01);
                sm[O_XTP + (e * 33 + pi1) * 2 + cgi]       = rnaf(n10);
                sm[O_XTP + ((e + 1) * 33 + pi1) * 2 + cgi] = rnaf(n11);
            } else {
                out[((size_t)b * 64 + ibase) * 128 + e]         = n00;
                out[((size_t)b * 64 + ibase) * 128 + e + 1]     = n01;
                out[((size_t)b * 64 + ibase + 8) * 128 + e]     = n10;
                out[((size_t)b * 64 + ibase + 8) * 128 + e + 1] = n11;
            }
        }
        __syncthreads();
    }
}

extern "C" void kernel_launch(void* const* d_in, const int* in_sizes, int n_in,
                              void* d_out, int out_size)
{
    const float* r  = (const float*)d_in[0];
    const float* Rn = (const float*)d_in[1];
    const float* et = (const float*)d_in[2];
    const float* ws = (const float*)d_in[3];
    const float* wa = (const float*)d_in[4];
    const float* wn = (const float*)d_in[5];
    const float* wu = (const float*)d_in[6];
    const float* bu = (const float*)d_in[7];
    const int*   at = (const int*)d_in[8];
    float* out = (float*)d_out;

    const int smem = SMF * (int)sizeof(float);   // 182,272 B
    cudaFuncSetAttribute(gnn, cudaFuncAttributeMaxDynamicSharedMemorySize, smem);
    prep<<<dim3(512, 3), 128>>>(et, at, wn, wu);
    gnn<<<512, NT, smem>>>(r, Rn, ws, wa, bu, out);
}